// round 2
// baseline (speedup 1.0000x reference)
#include <cuda_runtime.h>
#include <math.h>

// Problem constants (fixed-shape problem: B=4096, V=32000, fp32)
#define VDIM   32000
#define NV4    (VDIM / 4)
#define BMAX   4096
#define CAP    2048          // candidate capacity per row (~516 expected, huge margin)
#define ATHR   512           // threads for rowprep
#define NWARP_A (ATHR / 32)
#define BTHR   128           // threads for bisect (4 warps, 1 row per warp)
#define WPB    (BTHR / 32)

// Static scratch (no allocations allowed)
__device__ float g_cand[(size_t)BMAX * CAP];
__device__ int   g_cnt[BMAX];
__device__ float g_max[BMAX];
__device__ float g_tx[BMAX];
__device__ float g_rowloss[BMAX];

// ---------------------------------------------------------------------------
// Kernel 1: per-row max, sum(t*X), and deterministic candidate compaction.
// One CTA per row; full Xs row staged in dynamic SMEM (128 KB).
// ---------------------------------------------------------------------------
__global__ __launch_bounds__(ATHR) void rowprep_kernel(
    const float* __restrict__ logits, const float* __restrict__ targets)
{
    extern __shared__ float s_xs[];            // VDIM floats
    const int r    = blockIdx.x;
    const int t    = threadIdx.x;
    const int lane = t & 31;
    const int wid  = t >> 5;

    const float4* __restrict__ lg = reinterpret_cast<const float4*>(logits  + (size_t)r * VDIM);
    const float4* __restrict__ tg = reinterpret_cast<const float4*>(targets + (size_t)r * VDIM);
    float4* s4 = reinterpret_cast<float4*>(s_xs);

    float mx = -INFINITY;
    float tx = 0.0f;
    for (int j = t; j < NV4; j += ATHR) {
        float4 x  = lg[j];
        float4 tt = tg[j];
        float4 xs;
        xs.x = 0.5f * x.x; xs.y = 0.5f * x.y; xs.z = 0.5f * x.z; xs.w = 0.5f * x.w;
        s4[j] = xs;
        mx = fmaxf(mx, fmaxf(fmaxf(xs.x, xs.y), fmaxf(xs.z, xs.w)));
        tx += tt.x * x.x;
        tx += tt.y * x.y;
        tx += tt.z * x.z;
        tx += tt.w * x.w;
    }

    // Block reduce: max and sum (deterministic fixed tree)
    #pragma unroll
    for (int o = 16; o; o >>= 1) {
        mx = fmaxf(mx, __shfl_xor_sync(0xffffffffu, mx, o));
        tx += __shfl_xor_sync(0xffffffffu, tx, o);
    }
    __shared__ float s_m[NWARP_A], s_t[NWARP_A];
    __shared__ float s_bc[2];
    if (lane == 0) { s_m[wid] = mx; s_t[wid] = tx; }
    __syncthreads();
    if (t == 0) {
        float m = s_m[0], s = s_t[0];
        for (int w = 1; w < NWARP_A; ++w) { m = fmaxf(m, s_m[w]); s += s_t[w]; }
        s_bc[0] = m; s_bc[1] = s;
    }
    __syncthreads();
    const float rowmax = s_bc[0];
    const float txsum  = s_bc[1];
    const float thr    = rowmax - 1.0f;   // = tau_lo; elements <= thr never contribute

    // Count candidates per thread
    int cnt = 0;
    for (int j = t; j < NV4; j += ATHR) {
        float4 xs = s4[j];
        cnt += (xs.x > thr) + (xs.y > thr) + (xs.z > thr) + (xs.w > thr);
    }
    // Block exclusive scan (deterministic ordering -> deterministic fp sums later)
    int incl = cnt;
    #pragma unroll
    for (int o = 1; o < 32; o <<= 1) {
        int v = __shfl_up_sync(0xffffffffu, incl, o);
        if (lane >= o) incl += v;
    }
    __shared__ int s_wsum[NWARP_A];
    __shared__ int s_wbase[NWARP_A + 1];
    if (lane == 31) s_wsum[wid] = incl;
    __syncthreads();
    if (t == 0) {
        int run = 0;
        for (int w = 0; w < NWARP_A; ++w) { s_wbase[w] = run; run += s_wsum[w]; }
        s_wbase[NWARP_A] = run;
    }
    __syncthreads();

    int off = s_wbase[wid] + (incl - cnt);
    float* __restrict__ outc = g_cand + (size_t)r * CAP;
    for (int j = t; j < NV4; j += ATHR) {
        float4 xs = s4[j];
        if (xs.x > thr) { if (off < CAP) outc[off] = xs.x; off++; }
        if (xs.y > thr) { if (off < CAP) outc[off] = xs.y; off++; }
        if (xs.z > thr) { if (off < CAP) outc[off] = xs.z; off++; }
        if (xs.w > thr) { if (off < CAP) outc[off] = xs.w; off++; }
    }
    if (t == 0) {
        int total = s_wbase[NWARP_A];
        g_cnt[r] = total < CAP ? total : CAP;
        g_max[r] = rowmax;
        g_tx[r]  = txsum;
    }
}

// ---------------------------------------------------------------------------
// Kernel 2: bisection over candidates only. One warp per row.
// Exactly mirrors the reference update rule (f_m * f_lo >= 0, last tau_m).
// ---------------------------------------------------------------------------
__global__ __launch_bounds__(BTHR) void bisect_kernel(int B)
{
    __shared__ float s_c[WPB * CAP];          // 32 KB
    const int lane = threadIdx.x & 31;
    const int wid  = threadIdx.x >> 5;
    const int r    = blockIdx.x * WPB + wid;
    if (r >= B) return;

    float* cs = s_c + wid * CAP;
    const int n = g_cnt[r];
    const float* __restrict__ gc = g_cand + (size_t)r * CAP;
    for (int i = lane; i < n; i += 32) cs[i] = gc[i];
    __syncwarp();

    const float mx     = g_max[r];
    float       tau_lo = mx - 1.0f;
    const float tau_hi = mx - 0.00559016994f;   // (1/32000)^(alpha-1), alpha=1.5
    float       dm     = tau_hi - tau_lo;

    // f_lo (fixed across all iterations, per reference)
    float acc = 0.0f;
    for (int i = lane; i < n; i += 32) {
        float d = fmaxf(cs[i] - tau_lo, 0.0f);
        acc = fmaf(d, d, acc);
    }
    #pragma unroll
    for (int o = 16; o; o >>= 1) acc += __shfl_xor_sync(0xffffffffu, acc, o);
    const float f_lo = acc - 1.0f;

    float tau_m = tau_lo;
    for (int it = 0; it < 50; ++it) {
        dm *= 0.5f;
        tau_m = tau_lo + dm;
        if (tau_m == tau_lo) break;   // fp32 fixed point: remaining iterations are no-ops
        float a = 0.0f;
        for (int i = lane; i < n; i += 32) {
            float d = fmaxf(cs[i] - tau_m, 0.0f);
            a = fmaf(d, d, a);
        }
        #pragma unroll
        for (int o = 16; o; o >>= 1) a += __shfl_xor_sync(0xffffffffu, a, o);
        float f_m = a - 1.0f;
        if (f_m * f_lo >= 0.0f) tau_lo = tau_m;
    }

    // Final stats at last tau_m:
    //   p_i = z^2 (z = relu(Xs - tau_m)),  s2 = sum p,  s3 = sum z^3 = sum p^1.5
    //   sum(p*X) = 2 * sum(z^2 * Xs)      (X = 2*Xs)
    float s2 = 0.0f, s3 = 0.0f, sx = 0.0f;
    for (int i = lane; i < n; i += 32) {
        float xs = cs[i];
        float z  = fmaxf(xs - tau_m, 0.0f);
        float z2 = z * z;
        s2 += z2;
        s3 = fmaf(z2, z,  s3);
        sx = fmaf(z2, xs, sx);
    }
    #pragma unroll
    for (int o = 16; o; o >>= 1) {
        s2 += __shfl_xor_sync(0xffffffffu, s2, o);
        s3 += __shfl_xor_sync(0xffffffffu, s3, o);
        sx += __shfl_xor_sync(0xffffffffu, sx, o);
    }
    if (lane == 0) {
        // omega = (1 - sum(phat^1.5)) / (alpha*(alpha-1)) = (1 - s3/s2^1.5) * 4/3
        float omega = (1.0f - s3 / (s2 * sqrtf(s2))) * (4.0f / 3.0f);
        g_rowloss[r] = omega + 2.0f * sx / s2 - g_tx[r];
    }
}

// ---------------------------------------------------------------------------
// Kernel 3: mean over rows.
// ---------------------------------------------------------------------------
__global__ void reduce_kernel(float* __restrict__ out, int B)
{
    __shared__ float s[1024];
    float a = 0.0f;
    for (int i = threadIdx.x; i < B; i += 1024) a += g_rowloss[i];
    s[threadIdx.x] = a;
    __syncthreads();
    #pragma unroll
    for (int o = 512; o; o >>= 1) {
        if (threadIdx.x < o) s[threadIdx.x] += s[threadIdx.x + o];
        __syncthreads();
    }
    if (threadIdx.x == 0) out[0] = s[0] / (float)B;
}

extern "C" void kernel_launch(void* const* d_in, const int* in_sizes, int n_in,
                              void* d_out, int out_size)
{
    const float* logits  = (const float*)d_in[0];
    const float* targets = (const float*)d_in[1];
    int B = in_sizes[0] / VDIM;
    if (B > BMAX) B = BMAX;

    cudaFuncSetAttribute(rowprep_kernel,
                         cudaFuncAttributeMaxDynamicSharedMemorySize, VDIM * 4);

    rowprep_kernel<<<B, ATHR, VDIM * 4>>>(logits, targets);
    bisect_kernel<<<(B + WPB - 1) / WPB, BTHR>>>(B);
    reduce_kernel<<<1, 1024>>>((float*)d_out, B);
}

// round 3
// speedup vs baseline: 1.2196x; 1.2196x over previous
#include <cuda_runtime.h>
#include <math.h>

// Fixed-shape problem: B=4096, V=32000, fp32
#define VDIM   32000
#define NV4    (VDIM / 4)
#define BMAX   4096
#define CAP    2048          // global candidate capacity per row (~516 expected)
#define ATHR   256           // rowprep threads
#define NWARP_A (ATHR / 32)
#define WCAP   512           // per-warp SMEM candidate buffer (expected ~64)
#define BTHR   128           // bisect threads (4 warps, 1 row/warp)
#define WPB    (BTHR / 32)

__device__ float g_cand[(size_t)BMAX * CAP];
__device__ int   g_cnt[BMAX];
__device__ float g_max[BMAX];
__device__ float g_tx[BMAX];
__device__ float g_rowloss[BMAX];

// ---------------------------------------------------------------------------
// Kernel 1: per-row max + sum(t*X) (pass 1, streaming), then candidate
// compaction via a second read of logits (mostly L2-resident) with
// deterministic warp-ballot compaction into small SMEM buffers.
// No big SMEM staging -> 6-8 CTAs/SM so compute overlaps streaming.
// ---------------------------------------------------------------------------
__global__ __launch_bounds__(ATHR, 6) void rowprep_kernel(
    const float* __restrict__ logits, const float* __restrict__ targets)
{
    __shared__ float s_wbuf[NWARP_A][WCAP];    // 16 KB
    __shared__ float s_m[NWARP_A], s_t[NWARP_A];
    __shared__ float s_bc[2];
    __shared__ int   s_wsum[NWARP_A];
    __shared__ int   s_wbase[NWARP_A + 1];

    const int r     = blockIdx.x;
    const int t     = threadIdx.x;
    const int lane  = t & 31;
    const int wid   = t >> 5;
    const unsigned lmask = (1u << lane) - 1u;

    const float4* __restrict__ lg = reinterpret_cast<const float4*>(logits  + (size_t)r * VDIM);
    const float4* __restrict__ tg = reinterpret_cast<const float4*>(targets + (size_t)r * VDIM);

    // ---- Pass 1: max(Xs) and sum(t*X). logits -> default (stays in L2),
    //      targets -> streaming (evict-first, keep L2 for logits reuse).
    float mx = -INFINITY;
    float tx = 0.0f;
    for (int j = t; j < NV4; j += ATHR) {
        float4 x  = lg[j];
        float4 tt = __ldcs(&tg[j]);
        float4 xs;
        xs.x = 0.5f * x.x; xs.y = 0.5f * x.y; xs.z = 0.5f * x.z; xs.w = 0.5f * x.w;
        mx = fmaxf(mx, fmaxf(fmaxf(xs.x, xs.y), fmaxf(xs.z, xs.w)));
        tx = fmaf(tt.x, x.x, tx);
        tx = fmaf(tt.y, x.y, tx);
        tx = fmaf(tt.z, x.z, tx);
        tx = fmaf(tt.w, x.w, tx);
    }
    #pragma unroll
    for (int o = 16; o; o >>= 1) {
        mx = fmaxf(mx, __shfl_xor_sync(0xffffffffu, mx, o));
        tx += __shfl_xor_sync(0xffffffffu, tx, o);
    }
    if (lane == 0) { s_m[wid] = mx; s_t[wid] = tx; }
    __syncthreads();
    if (t == 0) {
        float m = s_m[0], s = s_t[0];
        for (int w = 1; w < NWARP_A; ++w) { m = fmaxf(m, s_m[w]); s += s_t[w]; }
        s_bc[0] = m; s_bc[1] = s;
    }
    __syncthreads();
    const float rowmax = s_bc[0];
    const float txsum  = s_bc[1];
    const float thr    = rowmax - 1.0f;   // elements <= thr never contribute

    // ---- Pass 2: re-read logits (L2 hit), warp-ballot compaction.
    float* wbuf = s_wbuf[wid];
    int wcnt = 0;
    for (int j = t; j < NV4; j += ATHR) {
        float4 x = __ldcs(&lg[j]);
        float v0 = 0.5f * x.x, v1 = 0.5f * x.y, v2 = 0.5f * x.z, v3 = 0.5f * x.w;
        unsigned m;
        m = __ballot_sync(0xffffffffu, v0 > thr);
        if (v0 > thr) { int p = wcnt + __popc(m & lmask); if (p < WCAP) wbuf[p] = v0; }
        wcnt += __popc(m);
        m = __ballot_sync(0xffffffffu, v1 > thr);
        if (v1 > thr) { int p = wcnt + __popc(m & lmask); if (p < WCAP) wbuf[p] = v1; }
        wcnt += __popc(m);
        m = __ballot_sync(0xffffffffu, v2 > thr);
        if (v2 > thr) { int p = wcnt + __popc(m & lmask); if (p < WCAP) wbuf[p] = v2; }
        wcnt += __popc(m);
        m = __ballot_sync(0xffffffffu, v3 > thr);
        if (v3 > thr) { int p = wcnt + __popc(m & lmask); if (p < WCAP) wbuf[p] = v3; }
        wcnt += __popc(m);
    }
    if (wcnt > WCAP) wcnt = WCAP;
    if (lane == 0) s_wsum[wid] = wcnt;
    __syncthreads();
    if (t == 0) {
        int run = 0;
        for (int w = 0; w < NWARP_A; ++w) { s_wbase[w] = run; run += s_wsum[w]; }
        s_wbase[NWARP_A] = run;
    }
    __syncthreads();

    // Copy warp buffers to global candidate array at scanned offsets.
    const int base = s_wbase[wid];
    float* __restrict__ outc = g_cand + (size_t)r * CAP;
    for (int i = lane; i < wcnt; i += 32) {
        int p = base + i;
        if (p < CAP) outc[p] = wbuf[i];
    }
    if (t == 0) {
        int total = s_wbase[NWARP_A];
        g_cnt[r] = total < CAP ? total : CAP;
        g_max[r] = rowmax;
        g_tx[r]  = txsum;
    }
}

// ---------------------------------------------------------------------------
// Kernel 2: bisection over candidates only. One warp per row.
// Mirrors the reference update rule (f_m * f_lo >= 0, last tau_m).
// ---------------------------------------------------------------------------
__global__ __launch_bounds__(BTHR) void bisect_kernel(int B)
{
    __shared__ float s_c[WPB * CAP];          // 32 KB
    const int lane = threadIdx.x & 31;
    const int wid  = threadIdx.x >> 5;
    const int r    = blockIdx.x * WPB + wid;
    if (r >= B) return;

    float* cs = s_c + wid * CAP;
    const int n = g_cnt[r];
    const float* __restrict__ gc = g_cand + (size_t)r * CAP;
    for (int i = lane; i < n; i += 32) cs[i] = gc[i];
    __syncwarp();

    const float mx     = g_max[r];
    float       tau_lo = mx - 1.0f;
    const float tau_hi = mx - 0.00559016994f;   // (1/32000)^(alpha-1), alpha=1.5
    float       dm     = tau_hi - tau_lo;

    float acc = 0.0f;
    for (int i = lane; i < n; i += 32) {
        float d = fmaxf(cs[i] - tau_lo, 0.0f);
        acc = fmaf(d, d, acc);
    }
    #pragma unroll
    for (int o = 16; o; o >>= 1) acc += __shfl_xor_sync(0xffffffffu, acc, o);
    const float f_lo = acc - 1.0f;

    float tau_m = tau_lo;
    for (int it = 0; it < 50; ++it) {
        dm *= 0.5f;
        tau_m = tau_lo + dm;
        if (tau_m == tau_lo) break;   // fp32 fixed point: rest are no-ops
        float a = 0.0f;
        for (int i = lane; i < n; i += 32) {
            float d = fmaxf(cs[i] - tau_m, 0.0f);
            a = fmaf(d, d, a);
        }
        #pragma unroll
        for (int o = 16; o; o >>= 1) a += __shfl_xor_sync(0xffffffffu, a, o);
        float f_m = a - 1.0f;
        if (f_m * f_lo >= 0.0f) tau_lo = tau_m;
    }

    float s2 = 0.0f, s3 = 0.0f, sx = 0.0f;
    for (int i = lane; i < n; i += 32) {
        float xs = cs[i];
        float z  = fmaxf(xs - tau_m, 0.0f);
        float z2 = z * z;
        s2 += z2;
        s3 = fmaf(z2, z,  s3);
        sx = fmaf(z2, xs, sx);
    }
    #pragma unroll
    for (int o = 16; o; o >>= 1) {
        s2 += __shfl_xor_sync(0xffffffffu, s2, o);
        s3 += __shfl_xor_sync(0xffffffffu, s3, o);
        sx += __shfl_xor_sync(0xffffffffu, sx, o);
    }
    if (lane == 0) {
        float omega = (1.0f - s3 / (s2 * sqrtf(s2))) * (4.0f / 3.0f);
        g_rowloss[r] = omega + 2.0f * sx / s2 - g_tx[r];
    }
}

// ---------------------------------------------------------------------------
// Kernel 3: mean over rows.
// ---------------------------------------------------------------------------
__global__ void reduce_kernel(float* __restrict__ out, int B)
{
    __shared__ float s[1024];
    float a = 0.0f;
    for (int i = threadIdx.x; i < B; i += 1024) a += g_rowloss[i];
    s[threadIdx.x] = a;
    __syncthreads();
    #pragma unroll
    for (int o = 512; o; o >>= 1) {
        if (threadIdx.x < o) s[threadIdx.x] += s[threadIdx.x + o];
        __syncthreads();
    }
    if (threadIdx.x == 0) out[0] = s[0] / (float)B;
}

extern "C" void kernel_launch(void* const* d_in, const int* in_sizes, int n_in,
                              void* d_out, int out_size)
{
    const float* logits  = (const float*)d_in[0];
    const float* targets = (const float*)d_in[1];
    int B = in_sizes[0] / VDIM;
    if (B > BMAX) B = BMAX;

    rowprep_kernel<<<B, ATHR>>>(logits, targets);
    bisect_kernel<<<(B + WPB - 1) / WPB, BTHR>>>(B);
    reduce_kernel<<<1, 1024>>>((float*)d_out, B);
}

// round 4
// speedup vs baseline: 1.2948x; 1.0617x over previous
#include <cuda_runtime.h>
#include <math.h>

// Fixed-shape problem: B=4096, V=32000, fp32
#define VDIM   32000
#define NV4    (VDIM / 4)      // 8000; NV4 % ATHR == 64 -> warps 0,1 do one extra
                               // iteration, warp-uniform (ballot-safe)
#define BMAX   4096
#define CAP    2048            // global candidate capacity per row (~516 expected)
#define ATHR   256             // rowprep threads
#define NWARP_A (ATHR / 32)
#define WCAP   768             // per-warp SMEM candidate buffer (expected ~290 peak)
#define BTHR   128             // bisect threads (4 warps, 1 row/warp)
#define WPB    (BTHR / 32)
#define FULLM  0xffffffffu

__device__ float g_cand[(size_t)BMAX * CAP];
__device__ int   g_cnt[BMAX];
__device__ float g_max[BMAX];
__device__ float g_tx[BMAX];
__device__ float g_rowloss[BMAX];

// Warp-collective in-place compaction of wbuf[0..cnt) keeping v > thr.
// Deterministic (warp-synchronous, fixed order).
__device__ __forceinline__ int warp_prune(float* wbuf, int cnt, float thr,
                                          int lane, unsigned lmask)
{
    int newcnt = 0;
    int bound = (cnt + 31) & ~31;
    for (int i = lane; i < bound; i += 32) {
        float v = (i < cnt) ? wbuf[i] : -INFINITY;
        bool keep = v > thr;
        unsigned m = __ballot_sync(FULLM, keep);
        int p = newcnt + __popc(m & lmask);
        __syncwarp();                 // all reads of this window before any write
        if (keep) wbuf[p] = v;
        __syncwarp();
        newcnt += __popc(m);
    }
    return newcnt;
}

// ---------------------------------------------------------------------------
// Kernel 1: SINGLE streaming pass. Computes row max, sum(t*X), and collects
// a superset of candidates (Xs > runningmax-1) into per-warp SMEM buffers.
// Final exact filter with rowmax-1 after the stream. 1.0 GB total traffic.
// ---------------------------------------------------------------------------
__global__ __launch_bounds__(ATHR, 6) void rowprep_kernel(
    const float* __restrict__ logits, const float* __restrict__ targets)
{
    __shared__ float s_wbuf[NWARP_A][WCAP];    // 24 KB
    __shared__ float s_m[NWARP_A], s_t[NWARP_A];
    __shared__ float s_bc[1];
    __shared__ int   s_wsum[NWARP_A];
    __shared__ int   s_wbase[NWARP_A + 1];

    const int r     = blockIdx.x;
    const int t     = threadIdx.x;
    const int lane  = t & 31;
    const int wid   = t >> 5;
    const unsigned lmask = (1u << lane) - 1u;

    const float4* __restrict__ lg = reinterpret_cast<const float4*>(logits  + (size_t)r * VDIM);
    const float4* __restrict__ tg = reinterpret_cast<const float4*>(targets + (size_t)r * VDIM);

    float* wbuf = s_wbuf[wid];
    float  thr  = -INFINITY;      // running conservative threshold (<= rowmax-1)
    float  lmax = -INFINITY;      // lane-local running max of Xs
    float  tx0 = 0.0f, tx1 = 0.0f;
    int    wcnt = 0;
    int    it   = 0;

    for (int j = t; j < NV4; j += ATHR, ++it) {
        float4 x  = __ldcs(&lg[j]);
        float4 tt = __ldcs(&tg[j]);
        float v0 = 0.5f * x.x, v1 = 0.5f * x.y, v2 = 0.5f * x.z, v3 = 0.5f * x.w;
        lmax = fmaxf(lmax, fmaxf(fmaxf(v0, v1), fmaxf(v2, v3)));
        tx0 = fmaf(tt.x, x.x, tx0);
        tx1 = fmaf(tt.y, x.y, tx1);
        tx0 = fmaf(tt.z, x.z, tx0);
        tx1 = fmaf(tt.w, x.w, tx1);

        // Safety prune (warp-uniform predicate: wcnt is warp-uniform)
        if (wcnt > WCAP - 130) {
            int c = wcnt < WCAP ? wcnt : WCAP;
            wcnt = warp_prune(wbuf, c, thr, lane, lmask);
        }

        // Deterministic ballot deposit of elements above the running threshold
        unsigned m;
        m = __ballot_sync(FULLM, v0 > thr);
        if (v0 > thr) { int p = wcnt + __popc(m & lmask); if (p < WCAP) wbuf[p] = v0; }
        wcnt += __popc(m);
        m = __ballot_sync(FULLM, v1 > thr);
        if (v1 > thr) { int p = wcnt + __popc(m & lmask); if (p < WCAP) wbuf[p] = v1; }
        wcnt += __popc(m);
        m = __ballot_sync(FULLM, v2 > thr);
        if (v2 > thr) { int p = wcnt + __popc(m & lmask); if (p < WCAP) wbuf[p] = v2; }
        wcnt += __popc(m);
        m = __ballot_sync(FULLM, v3 > thr);
        if (v3 > thr) { int p = wcnt + __popc(m & lmask); if (p < WCAP) wbuf[p] = v3; }
        wcnt += __popc(m);

        // Tighten the running threshold (every iter early, then every 4th)
        if (it < 4 || (it & 3) == 3) {
            float wm = lmax;
            #pragma unroll
            for (int o = 16; o; o >>= 1)
                wm = fmaxf(wm, __shfl_xor_sync(FULLM, wm, o));
            thr = wm - 1.0f;
        }
    }

    // ---- Block reductions: exact row max, sum(t*X)
    float tx = tx0 + tx1;
    float wm = lmax;
    #pragma unroll
    for (int o = 16; o; o >>= 1) {
        wm = fmaxf(wm, __shfl_xor_sync(FULLM, wm, o));
        tx += __shfl_xor_sync(FULLM, tx, o);
    }
    if (lane == 0) { s_m[wid] = wm; s_t[wid] = tx; }
    __syncthreads();
    if (t == 0) {
        float m = s_m[0], s = s_t[0];
        for (int w = 1; w < NWARP_A; ++w) { m = fmaxf(m, s_m[w]); s += s_t[w]; }
        s_bc[0] = m;
        g_max[r] = m;
        g_tx[r]  = s;
    }
    __syncthreads();
    const float rowmax = s_bc[0];
    const float thrF   = rowmax - 1.0f;

    // ---- Exact final filter of each warp buffer, then block scan + writeout
    {
        int c = wcnt < WCAP ? wcnt : WCAP;
        wcnt = warp_prune(wbuf, c, thrF, lane, lmask);
    }
    if (lane == 0) s_wsum[wid] = wcnt;
    __syncthreads();
    if (t == 0) {
        int run = 0;
        for (int w = 0; w < NWARP_A; ++w) { s_wbase[w] = run; run += s_wsum[w]; }
        s_wbase[NWARP_A] = run;
        g_cnt[r] = run < CAP ? run : CAP;
    }
    __syncthreads();

    const int base = s_wbase[wid];
    float* __restrict__ outc = g_cand + (size_t)r * CAP;
    for (int i = lane; i < wcnt; i += 32) {
        int p = base + i;
        if (p < CAP) outc[p] = wbuf[i];
    }
}

// ---------------------------------------------------------------------------
// Kernel 2: bisection over candidates only. One warp per row.
// Mirrors the reference update rule (f_m * f_lo >= 0, last tau_m).
// ---------------------------------------------------------------------------
__global__ __launch_bounds__(BTHR) void bisect_kernel(int B)
{
    __shared__ float s_c[WPB * CAP];          // 32 KB
    const int lane = threadIdx.x & 31;
    const int wid  = threadIdx.x >> 5;
    const int r    = blockIdx.x * WPB + wid;
    if (r >= B) return;

    float* cs = s_c + wid * CAP;
    const int n = g_cnt[r];
    const float* __restrict__ gc = g_cand + (size_t)r * CAP;
    for (int i = lane; i < n; i += 32) cs[i] = gc[i];
    __syncwarp();

    const float mx     = g_max[r];
    float       tau_lo = mx - 1.0f;
    const float tau_hi = mx - 0.00559016994f;   // (1/32000)^(alpha-1), alpha=1.5
    float       dm     = tau_hi - tau_lo;

    float acc = 0.0f;
    for (int i = lane; i < n; i += 32) {
        float d = fmaxf(cs[i] - tau_lo, 0.0f);
        acc = fmaf(d, d, acc);
    }
    #pragma unroll
    for (int o = 16; o; o >>= 1) acc += __shfl_xor_sync(FULLM, acc, o);
    const float f_lo = acc - 1.0f;

    float tau_m = tau_lo;
    for (int itr = 0; itr < 50; ++itr) {
        dm *= 0.5f;
        tau_m = tau_lo + dm;
        if (tau_m == tau_lo) break;   // fp32 fixed point: rest are no-ops
        float a = 0.0f;
        for (int i = lane; i < n; i += 32) {
            float d = fmaxf(cs[i] - tau_m, 0.0f);
            a = fmaf(d, d, a);
        }
        #pragma unroll
        for (int o = 16; o; o >>= 1) a += __shfl_xor_sync(FULLM, a, o);
        float f_m = a - 1.0f;
        if (f_m * f_lo >= 0.0f) tau_lo = tau_m;
    }

    float s2 = 0.0f, s3 = 0.0f, sx = 0.0f;
    for (int i = lane; i < n; i += 32) {
        float xs = cs[i];
        float z  = fmaxf(xs - tau_m, 0.0f);
        float z2 = z * z;
        s2 += z2;
        s3 = fmaf(z2, z,  s3);
        sx = fmaf(z2, xs, sx);
    }
    #pragma unroll
    for (int o = 16; o; o >>= 1) {
        s2 += __shfl_xor_sync(FULLM, s2, o);
        s3 += __shfl_xor_sync(FULLM, s3, o);
        sx += __shfl_xor_sync(FULLM, sx, o);
    }
    if (lane == 0) {
        float omega = (1.0f - s3 / (s2 * sqrtf(s2))) * (4.0f / 3.0f);
        g_rowloss[r] = omega + 2.0f * sx / s2 - g_tx[r];
    }
}

// ---------------------------------------------------------------------------
// Kernel 3: mean over rows.
// ---------------------------------------------------------------------------
__global__ void reduce_kernel(float* __restrict__ out, int B)
{
    __shared__ float s[1024];
    float a = 0.0f;
    for (int i = threadIdx.x; i < B; i += 1024) a += g_rowloss[i];
    s[threadIdx.x] = a;
    __syncthreads();
    #pragma unroll
    for (int o = 512; o; o >>= 1) {
        if (threadIdx.x < o) s[threadIdx.x] += s[threadIdx.x + o];
        __syncthreads();
    }
    if (threadIdx.x == 0) out[0] = s[0] / (float)B;
}

extern "C" void kernel_launch(void* const* d_in, const int* in_sizes, int n_in,
                              void* d_out, int out_size)
{
    const float* logits  = (const float*)d_in[0];
    const float* targets = (const float*)d_in[1];
    int B = in_sizes[0] / VDIM;
    if (B > BMAX) B = BMAX;

    rowprep_kernel<<<B, ATHR>>>(logits, targets);
    bisect_kernel<<<(B + WPB - 1) / WPB, BTHR>>>(B);
    reduce_kernel<<<1, 1024>>>((float*)d_out, B);
}

// round 5
// speedup vs baseline: 1.7039x; 1.3159x over previous
#include <cuda_runtime.h>
#include <math.h>

// Fixed-shape problem: B=4096, V=32000, fp32
#define VDIM   32000
#define NV4    (VDIM / 4)      // 8000
#define BMAX   4096
#define CAP    2048            // global candidate capacity per row (~516 expected)
#define ATHR   256             // rowprep threads
#define NWARP_A (ATHR / 32)
#define WCAP   768             // per-warp SMEM candidate buffer
#define BTHR   128             // bisect threads (4 warps, 1 row/warp)
#define WPB    (BTHR / 32)
#define FULLM  0xffffffffu

__device__ float g_cand[(size_t)BMAX * CAP];
__device__ int   g_cnt[BMAX];
__device__ float g_max[BMAX];   // raw-X row max
__device__ float g_tx[BMAX];
__device__ float g_rowloss[BMAX];

// Warp-collective in-place compaction of wbuf[0..cnt) keeping v > thr.
__device__ __forceinline__ int warp_prune(float* wbuf, int cnt, float thr,
                                          int lane, unsigned lmask)
{
    int newcnt = 0;
    int bound = (cnt + 31) & ~31;
    for (int i = lane; i < bound; i += 32) {
        float v = (i < cnt) ? wbuf[i] : -INFINITY;
        bool keep = v > thr;
        unsigned m = __ballot_sync(FULLM, keep);
        int p = newcnt + __popc(m & lmask);
        __syncwarp();
        if (keep) wbuf[p] = v;
        __syncwarp();
        newcnt += __popc(m);
    }
    return newcnt;
}

// Deterministic ballot deposit of one float4's elements above thr (raw X).
__device__ __forceinline__ void deposit4(const float4& x, float thr,
                                         float* wbuf, int& wcnt,
                                         int lane, unsigned lmask)
{
    unsigned m;
    m = __ballot_sync(FULLM, x.x > thr);
    if (x.x > thr) { int p = wcnt + __popc(m & lmask); if (p < WCAP) wbuf[p] = x.x; }
    wcnt += __popc(m);
    m = __ballot_sync(FULLM, x.y > thr);
    if (x.y > thr) { int p = wcnt + __popc(m & lmask); if (p < WCAP) wbuf[p] = x.y; }
    wcnt += __popc(m);
    m = __ballot_sync(FULLM, x.z > thr);
    if (x.z > thr) { int p = wcnt + __popc(m & lmask); if (p < WCAP) wbuf[p] = x.z; }
    wcnt += __popc(m);
    m = __ballot_sync(FULLM, x.w > thr);
    if (x.w > thr) { int p = wcnt + __popc(m & lmask); if (p < WCAP) wbuf[p] = x.w; }
    wcnt += __popc(m);
}

// ---------------------------------------------------------------------------
// Kernel 1: SINGLE streaming pass, unrolled x2 with loads batched first
// (MLP=4 per warp). Raw-X units (no scaling in the hot loop). Collects a
// superset of candidates (x > runningmaxX - 2) into per-warp SMEM buffers;
// exact final filter with rowmaxX - 2 after the stream.
// ---------------------------------------------------------------------------
__global__ __launch_bounds__(ATHR) void rowprep_kernel(
    const float* __restrict__ logits, const float* __restrict__ targets)
{
    __shared__ float s_wbuf[NWARP_A][WCAP];    // 24 KB
    __shared__ float s_m[NWARP_A], s_t[NWARP_A];
    __shared__ float s_bc[1];
    __shared__ int   s_wsum[NWARP_A];
    __shared__ int   s_wbase[NWARP_A + 1];

    const int r     = blockIdx.x;
    const int t     = threadIdx.x;
    const int lane  = t & 31;
    const int wid   = t >> 5;
    const unsigned lmask = (1u << lane) - 1u;

    const float4* __restrict__ lg = reinterpret_cast<const float4*>(logits  + (size_t)r * VDIM);
    const float4* __restrict__ tg = reinterpret_cast<const float4*>(targets + (size_t)r * VDIM);

    float* wbuf = s_wbuf[wid];
    float  thr  = -INFINITY;      // running threshold in raw-X units (<= maxX-2)
    float  lmax = -INFINITY;      // lane-local running max of raw X
    float  tx0 = 0.0f, tx1 = 0.0f;
    int    wcnt = 0;
    int    it   = 0;

    for (int j = t; j < NV4; j += 2 * ATHR, ++it) {
        const bool two = (j + ATHR < NV4);   // warp-uniform (NV4 % 32 == 0)
        // ---- batch all loads first (MLP) ----
        float4 xa = __ldcs(&lg[j]);
        float4 ta = __ldcs(&tg[j]);
        float4 xb = make_float4(-INFINITY, -INFINITY, -INFINITY, -INFINITY);
        float4 tb = make_float4(0.f, 0.f, 0.f, 0.f);
        if (two) {
            xb = __ldcs(&lg[j + ATHR]);
            tb = __ldcs(&tg[j + ATHR]);
        }

        // ---- running max ----
        float vma = fmaxf(fmaxf(xa.x, xa.y), fmaxf(xa.z, xa.w));
        float vmb = fmaxf(fmaxf(xb.x, xb.y), fmaxf(xb.z, xb.w));
        lmax = fmaxf(lmax, fmaxf(vma, vmb));

        // ---- sum(t*X), two accumulators ----
        tx0 = fmaf(ta.x, xa.x, tx0);
        tx1 = fmaf(ta.y, xa.y, tx1);
        tx0 = fmaf(ta.z, xa.z, tx0);
        tx1 = fmaf(ta.w, xa.w, tx1);
        if (two) {
            tx0 = fmaf(tb.x, xb.x, tx0);
            tx1 = fmaf(tb.y, xb.y, tx1);
            tx0 = fmaf(tb.z, xb.z, tx0);
            tx1 = fmaf(tb.w, xb.w, tx1);
        }

        // ---- safety prune (warp-uniform predicate) ----
        if (wcnt > WCAP - 260) {
            int c = wcnt < WCAP ? wcnt : WCAP;
            wcnt = warp_prune(wbuf, c, thr, lane, lmask);
        }

        // ---- deposits ----
        deposit4(xa, thr, wbuf, wcnt, lane, lmask);
        if (two) deposit4(xb, thr, wbuf, wcnt, lane, lmask);

        // ---- tighten running threshold ----
        if (it < 4 || (it & 1)) {
            float wm = lmax;
            #pragma unroll
            for (int o = 16; o; o >>= 1)
                wm = fmaxf(wm, __shfl_xor_sync(FULLM, wm, o));
            thr = wm - 2.0f;
        }
    }

    // ---- block reductions: exact row max (raw X), sum(t*X) ----
    float tx = tx0 + tx1;
    float wm = lmax;
    #pragma unroll
    for (int o = 16; o; o >>= 1) {
        wm = fmaxf(wm, __shfl_xor_sync(FULLM, wm, o));
        tx += __shfl_xor_sync(FULLM, tx, o);
    }
    if (lane == 0) { s_m[wid] = wm; s_t[wid] = tx; }
    __syncthreads();
    if (t == 0) {
        float m = s_m[0], s = s_t[0];
        for (int w = 1; w < NWARP_A; ++w) { m = fmaxf(m, s_m[w]); s += s_t[w]; }
        s_bc[0] = m;
        g_max[r] = m;
        g_tx[r]  = s;
    }
    __syncthreads();
    const float thrF = s_bc[0] - 2.0f;   // raw-X final threshold

    // ---- exact final filter, block scan, writeout ----
    {
        int c = wcnt < WCAP ? wcnt : WCAP;
        wcnt = warp_prune(wbuf, c, thrF, lane, lmask);
    }
    if (lane == 0) s_wsum[wid] = wcnt;
    __syncthreads();
    if (t == 0) {
        int run = 0;
        for (int w = 0; w < NWARP_A; ++w) { s_wbase[w] = run; run += s_wsum[w]; }
        s_wbase[NWARP_A] = run;
        g_cnt[r] = run < CAP ? run : CAP;
    }
    __syncthreads();

    const int base = s_wbase[wid];
    float* __restrict__ outc = g_cand + (size_t)r * CAP;
    for (int i = lane; i < wcnt; i += 32) {
        int p = base + i;
        if (p < CAP) outc[p] = wbuf[i];
    }
}

// ---------------------------------------------------------------------------
// Kernel 2: bisection over candidates only (one warp per row). Candidates
// stored as raw X; convert with exact *0.5 at load. Mirrors the reference
// update rule (f_m * f_lo >= 0, last tau_m).
// ---------------------------------------------------------------------------
__global__ __launch_bounds__(BTHR) void bisect_kernel(int B)
{
    __shared__ float s_c[WPB * CAP];          // 32 KB
    const int lane = threadIdx.x & 31;
    const int wid  = threadIdx.x >> 5;
    const int r    = blockIdx.x * WPB + wid;
    if (r >= B) return;

    float* cs = s_c + wid * CAP;
    const int n = g_cnt[r];
    const float* __restrict__ gc = g_cand + (size_t)r * CAP;
    for (int i = lane; i < n; i += 32) cs[i] = 0.5f * gc[i];
    __syncwarp();

    const float mx     = 0.5f * g_max[r];       // exact: matches reference max(Xs)
    float       tau_lo = mx - 1.0f;
    const float tau_hi = mx - 0.00559016994f;   // (1/32000)^(alpha-1), alpha=1.5
    float       dm     = tau_hi - tau_lo;

    float acc = 0.0f;
    for (int i = lane; i < n; i += 32) {
        float d = fmaxf(cs[i] - tau_lo, 0.0f);
        acc = fmaf(d, d, acc);
    }
    #pragma unroll
    for (int o = 16; o; o >>= 1) acc += __shfl_xor_sync(FULLM, acc, o);
    const float f_lo = acc - 1.0f;

    float tau_m = tau_lo;
    for (int itr = 0; itr < 50; ++itr) {
        dm *= 0.5f;
        tau_m = tau_lo + dm;
        if (tau_m == tau_lo) break;   // fp32 fixed point: rest are no-ops
        float a = 0.0f;
        for (int i = lane; i < n; i += 32) {
            float d = fmaxf(cs[i] - tau_m, 0.0f);
            a = fmaf(d, d, a);
        }
        #pragma unroll
        for (int o = 16; o; o >>= 1) a += __shfl_xor_sync(FULLM, a, o);
        float f_m = a - 1.0f;
        if (f_m * f_lo >= 0.0f) tau_lo = tau_m;
    }

    float s2 = 0.0f, s3 = 0.0f, sx = 0.0f;
    for (int i = lane; i < n; i += 32) {
        float xs = cs[i];
        float z  = fmaxf(xs - tau_m, 0.0f);
        float z2 = z * z;
        s2 += z2;
        s3 = fmaf(z2, z,  s3);
        sx = fmaf(z2, xs, sx);
    }
    #pragma unroll
    for (int o = 16; o; o >>= 1) {
        s2 += __shfl_xor_sync(FULLM, s2, o);
        s3 += __shfl_xor_sync(FULLM, s3, o);
        sx += __shfl_xor_sync(FULLM, sx, o);
    }
    if (lane == 0) {
        float omega = (1.0f - s3 / (s2 * sqrtf(s2))) * (4.0f / 3.0f);
        g_rowloss[r] = omega + 2.0f * sx / s2 - g_tx[r];
    }
}

// ---------------------------------------------------------------------------
// Kernel 3: mean over rows.
// ---------------------------------------------------------------------------
__global__ void reduce_kernel(float* __restrict__ out, int B)
{
    __shared__ float s[1024];
    float a = 0.0f;
    for (int i = threadIdx.x; i < B; i += 1024) a += g_rowloss[i];
    s[threadIdx.x] = a;
    __syncthreads();
    #pragma unroll
    for (int o = 512; o; o >>= 1) {
        if (threadIdx.x < o) s[threadIdx.x] += s[threadIdx.x + o];
        __syncthreads();
    }
    if (threadIdx.x == 0) out[0] = s[0] / (float)B;
}

extern "C" void kernel_launch(void* const* d_in, const int* in_sizes, int n_in,
                              void* d_out, int out_size)
{
    const float* logits  = (const float*)d_in[0];
    const float* targets = (const float*)d_in[1];
    int B = in_sizes[0] / VDIM;
    if (B > BMAX) B = BMAX;

    rowprep_kernel<<<B, ATHR>>>(logits, targets);
    bisect_kernel<<<(B + WPB - 1) / WPB, BTHR>>>(B);
    reduce_kernel<<<1, 1024>>>((float*)d_out, B);
}